// round 2
// baseline (speedup 1.0000x reference)
#include <cuda_runtime.h>
#include <cuda_bf16.h>
#include <math.h>

// Problem shape (fixed by the dataset)
#define NMAX   100000
#define DIN    256
#define DH     64
#define DOUT   4

// Scratch (static __device__ arrays -- no allocation allowed)
__device__ float g_yl[NMAX * DH];    // x @ W1_l
__device__ float g_yr[NMAX * DH];    // x @ W1_r
__device__ float g_acc1[NMAX * DH];  // edge-aggregated y_l
__device__ float g_deg[NMAX];        // in-degree (float)
__device__ float g_zl[NMAX * DOUT];  // h @ W2_l
__device__ float g_zr[NMAX * DOUT];  // h @ W2_r
__device__ float g_acc2[NMAX * DOUT];

// ---------------------------------------------------------------------------
// Zero the accumulators + degree
// ---------------------------------------------------------------------------
__global__ void zero_kernel(int n_nodes) {
    int i = blockIdx.x * blockDim.x + threadIdx.x;
    int big = n_nodes * DH;
    if (i < big)           g_acc1[i] = 0.0f;
    if (i < n_nodes * DOUT) g_acc2[i] = 0.0f;
    if (i < n_nodes)       g_deg[i]  = 0.0f;
}

// ---------------------------------------------------------------------------
// GEMM1: y[N,128] = x[N,256] @ [W1_l | W1_r]  (cols 0..63 -> yl, 64..127 -> yr)
// BM=64, BN=128, BK=16; 128 threads, 8x8 register tile per thread.
// ---------------------------------------------------------------------------
__global__ __launch_bounds__(128) void gemm1_kernel(
    const float* __restrict__ x,
    const float* __restrict__ Wl,
    const float* __restrict__ Wr,
    int n_nodes)
{
    __shared__ float As[16][64];    // As[k][m]
    __shared__ float Bs[16][128];   // Bs[k][n]

    const int tid = threadIdx.x;
    const int m0  = blockIdx.x * 64;
    const int ty  = tid >> 4;       // 0..7  (M direction)
    const int tx  = tid & 15;       // 0..15 (N direction)

    const int aRow  = tid >> 2;       // 0..31
    const int aCol4 = (tid & 3) * 4;  // 0,4,8,12

    float acc[8][8];
#pragma unroll
    for (int i = 0; i < 8; i++)
#pragma unroll
        for (int j = 0; j < 8; j++) acc[i][j] = 0.0f;

    for (int kb = 0; kb < DIN; kb += 16) {
        // Load A tile (64 x 16), transposed into As[k][m], float4 global loads
#pragma unroll
        for (int p = 0; p < 2; p++) {
            int m = aRow + p * 32;
            float4 v = make_float4(0.f, 0.f, 0.f, 0.f);
            int gm = m0 + m;
            if (gm < n_nodes)
                v = *reinterpret_cast<const float4*>(&x[(size_t)gm * DIN + kb + aCol4]);
            As[aCol4 + 0][m] = v.x;
            As[aCol4 + 1][m] = v.y;
            As[aCol4 + 2][m] = v.z;
            As[aCol4 + 3][m] = v.w;
        }
        // Load B tile (16 x 128): column j<64 from Wl, else Wr
#pragma unroll
        for (int kk = 0; kk < 16; kk++) {
            int kg = kb + kk;
            float w = (tid < 64) ? Wl[kg * DH + tid] : Wr[kg * DH + (tid - 64)];
            Bs[kk][tid] = w;
        }
        __syncthreads();

#pragma unroll
        for (int k = 0; k < 16; k++) {
            float a[8], b[8];
            float4 a0 = *reinterpret_cast<const float4*>(&As[k][ty * 8]);
            float4 a1 = *reinterpret_cast<const float4*>(&As[k][ty * 8 + 4]);
            a[0]=a0.x; a[1]=a0.y; a[2]=a0.z; a[3]=a0.w;
            a[4]=a1.x; a[5]=a1.y; a[6]=a1.z; a[7]=a1.w;
            float4 b0 = *reinterpret_cast<const float4*>(&Bs[k][tx * 8]);
            float4 b1 = *reinterpret_cast<const float4*>(&Bs[k][tx * 8 + 4]);
            b[0]=b0.x; b[1]=b0.y; b[2]=b0.z; b[3]=b0.w;
            b[4]=b1.x; b[5]=b1.y; b[6]=b1.z; b[7]=b1.w;
#pragma unroll
            for (int i = 0; i < 8; i++)
#pragma unroll
                for (int j = 0; j < 8; j++)
                    acc[i][j] = fmaf(a[i], b[j], acc[i][j]);
        }
        __syncthreads();
    }

    // Store: n<64 -> yl, n>=64 -> yr
#pragma unroll
    for (int i = 0; i < 8; i++) {
        int gm = m0 + ty * 8 + i;
        if (gm >= n_nodes) continue;
#pragma unroll
        for (int j = 0; j < 8; j++) {
            int n = tx * 8 + j;
            if (n < DH) g_yl[(size_t)gm * DH + n]        = acc[i][j];
            else        g_yr[(size_t)gm * DH + (n - DH)] = acc[i][j];
        }
    }
}

// ---------------------------------------------------------------------------
// Degree: deg[dst[e]] += 1
// ---------------------------------------------------------------------------
__global__ void deg_kernel(const int* __restrict__ dst, int E) {
    int e = blockIdx.x * blockDim.x + threadIdx.x;
    if (e < E) atomicAdd(&g_deg[dst[e]], 1.0f);
}

// ---------------------------------------------------------------------------
// Scatter1: acc1[dst] += yl[src]   (64 floats per edge, one thread per float)
// ---------------------------------------------------------------------------
__global__ void scatter1_kernel(const int* __restrict__ src,
                                const int* __restrict__ dst, int E) {
    int t = blockIdx.x * blockDim.x + threadIdx.x;
    int e = t >> 6;
    if (e >= E) return;
    int f = t & 63;
    int s = __ldg(&src[e]);
    int d = __ldg(&dst[e]);
    atomicAdd(&g_acc1[(size_t)d * DH + f], g_yl[(size_t)s * DH + f]);
}

// ---------------------------------------------------------------------------
// Combine1 + layer-2 transform, fused:
//   out1 = acc1/max(deg,1) + b1 + yr ; h = relu(out1 / max(||out1||,eps))
//   zl = h @ W2_l ; zr = h @ W2_r
// 256 threads = 4 nodes/block, 64 threads/node.
// ---------------------------------------------------------------------------
__global__ __launch_bounds__(256) void combine1_gemm2_kernel(
    const float* __restrict__ b1,
    const float* __restrict__ W2l,
    const float* __restrict__ W2r,
    int n_nodes)
{
    __shared__ float sW[DH * 8];     // [k][j]: j<4 = W2l col, j>=4 = W2r col
    __shared__ float sh[4][DH];
    __shared__ float swsum[4][2];

    int tid = threadIdx.x;
    for (int i = tid; i < DH * 8; i += 256) {
        int k = i >> 3, j = i & 7;
        sW[i] = (j < 4) ? W2l[k * DOUT + j] : W2r[k * DOUT + (j - 4)];
    }

    int nl = tid >> 6;          // node within block 0..3
    int f  = tid & 63;          // feature
    int n  = blockIdx.x * 4 + nl;

    float val = 0.0f;
    if (n < n_nodes) {
        float d = fmaxf(g_deg[n], 1.0f);
        val = g_acc1[(size_t)n * DH + f] / d + b1[f] + g_yr[(size_t)n * DH + f];
    }
    float sq = val * val;
#pragma unroll
    for (int o = 16; o > 0; o >>= 1) sq += __shfl_xor_sync(0xffffffffu, sq, o);
    if ((tid & 31) == 0) swsum[nl][(f >> 5)] = sq;
    __syncthreads();

    float norm = sqrtf(swsum[nl][0] + swsum[nl][1]);
    float h = fmaxf(val / fmaxf(norm, 1e-12f), 0.0f);
    sh[nl][f] = h;
    __syncthreads();

    if (f < 8 && n < n_nodes) {
        float a = 0.0f;
#pragma unroll
        for (int k = 0; k < DH; k++) a = fmaf(sh[nl][k], sW[k * 8 + f], a);
        if (f < 4) g_zl[(size_t)n * DOUT + f]       = a;
        else       g_zr[(size_t)n * DOUT + (f - 4)] = a;
    }
}

// ---------------------------------------------------------------------------
// Scatter2: acc2[dst] += zl[src]   (4 floats per edge)
// ---------------------------------------------------------------------------
__global__ void scatter2_kernel(const int* __restrict__ src,
                                const int* __restrict__ dst, int E) {
    int t = blockIdx.x * blockDim.x + threadIdx.x;
    int e = t >> 2;
    if (e >= E) return;
    int f = t & 3;
    int s = __ldg(&src[e]);
    int d = __ldg(&dst[e]);
    atomicAdd(&g_acc2[d * DOUT + f], g_zl[s * DOUT + f]);
}

// ---------------------------------------------------------------------------
// Combine2: out = normalize(acc2/max(deg,1) + b2 + zr)
// ---------------------------------------------------------------------------
__global__ void combine2_kernel(const float* __restrict__ b2,
                                float* __restrict__ out, int n_nodes) {
    int n = blockIdx.x * blockDim.x + threadIdx.x;
    if (n >= n_nodes) return;
    float d = fmaxf(g_deg[n], 1.0f);
    float4 a = *reinterpret_cast<const float4*>(&g_acc2[n * DOUT]);
    float4 r = *reinterpret_cast<const float4*>(&g_zr[n * DOUT]);
    float v0 = a.x / d + b2[0] + r.x;
    float v1 = a.y / d + b2[1] + r.y;
    float v2 = a.z / d + b2[2] + r.z;
    float v3 = a.w / d + b2[3] + r.w;
    float norm = fmaxf(sqrtf(v0 * v0 + v1 * v1 + v2 * v2 + v3 * v3), 1e-12f);
    float4 o = make_float4(v0 / norm, v1 / norm, v2 / norm, v3 / norm);
    *reinterpret_cast<float4*>(&out[n * DOUT]) = o;
}

// ---------------------------------------------------------------------------
// Launch
// inputs: x[N*256] f32, edge_index[2*E] i32, W1_l[256*64], b1_l[64],
//         W1_r[256*64], W2_l[64*4], b2_l[4], W2_r[64*4]
// ---------------------------------------------------------------------------
extern "C" void kernel_launch(void* const* d_in, const int* in_sizes, int n_in,
                              void* d_out, int out_size) {
    const float* x   = (const float*)d_in[0];
    const int*   ei  = (const int*)  d_in[1];
    const float* W1l = (const float*)d_in[2];
    const float* b1  = (const float*)d_in[3];
    const float* W1r = (const float*)d_in[4];
    const float* W2l = (const float*)d_in[5];
    const float* b2  = (const float*)d_in[6];
    const float* W2r = (const float*)d_in[7];
    float* out = (float*)d_out;

    const int N = in_sizes[0] / DIN;      // 100000
    const int E = in_sizes[1] / 2;        // 320000
    const int* src = ei;
    const int* dst = ei + E;

    // 1. zero accumulators
    zero_kernel<<<(N * DH + 255) / 256, 256>>>(N);
    // 2. y = x @ [W1_l | W1_r]
    gemm1_kernel<<<(N + 63) / 64, 128>>>(x, W1l, W1r, N);
    // 3. degrees
    deg_kernel<<<(E + 255) / 256, 256>>>(dst, E);
    // 4. aggregate in 64-dim space
    scatter1_kernel<<<((size_t)E * DH + 255) / 256, 256>>>(src, dst, E);
    // 5. normalize + relu + layer-2 transform (fused)
    combine1_gemm2_kernel<<<(N + 3) / 4, 256>>>(b1, W2l, W2r, N);
    // 6. aggregate in 4-dim space
    scatter2_kernel<<<((size_t)E * DOUT + 255) / 256, 256>>>(src, dst, E);
    // 7. final combine + normalize
    combine2_kernel<<<(N + 255) / 256, 256>>>(b2, out, N);
}

// round 6
// speedup vs baseline: 1.8899x; 1.8899x over previous
#include <cuda_runtime.h>
#include <cuda_bf16.h>
#include <math.h>

#define NMAX   100000
#define DIN    256
#define DH     64
#define DOUT   4

// Scratch (static __device__ arrays -- no allocation allowed)
__device__ float g_yl[NMAX * DH];      // x @ W1_l
__device__ float g_yr[NMAX * DH];      // x @ W1_r
__device__ float g_acc1[NMAX * DH];    // edge-aggregated y_l
__device__ float g_deg[NMAX];          // in-degree (float)
__device__ float g_zl[NMAX * DOUT];    // h @ W2_l
__device__ float g_zr[NMAX * DOUT];    // h @ W2_r
__device__ float g_acc2[NMAX * DOUT];
__device__ unsigned g_Btf[DIN * 128];  // tf32-converted [W1_l | W1_r], [k][n]

__device__ __forceinline__ unsigned f2tf32(float f) {
    unsigned r;
    asm("cvt.rna.tf32.f32 %0, %1;" : "=r"(r) : "f"(f));
    return r;
}

// ---------------------------------------------------------------------------
// Zero accumulators + degree (vectorized)
// ---------------------------------------------------------------------------
__global__ void zero_kernel(int n_nodes) {
    int i = blockIdx.x * blockDim.x + threadIdx.x;
    float4 z = make_float4(0.f, 0.f, 0.f, 0.f);
    if (i < n_nodes * (DH / 4)) reinterpret_cast<float4*>(g_acc1)[i] = z;
    if (i < n_nodes)            reinterpret_cast<float4*>(g_acc2)[i] = z;  // DOUT==4
    if (i < n_nodes)            g_deg[i] = 0.0f;
}

// ---------------------------------------------------------------------------
// Pre-convert B = [W1_l | W1_r] to tf32 (RNA), layout [k][n], n in 0..127
// ---------------------------------------------------------------------------
__global__ void btf_kernel(const float* __restrict__ Wl,
                           const float* __restrict__ Wr) {
    int i = blockIdx.x * blockDim.x + threadIdx.x;
    if (i >= DIN * 128) return;
    int k = i >> 7, n = i & 127;
    float v = (n < DH) ? Wl[k * DH + n] : Wr[k * DH + (n - DH)];
    g_Btf[i] = f2tf32(v);
}

// ---------------------------------------------------------------------------
// GEMM1 (tf32 tensor cores): y[N,128] = x[N,256] @ [W1_l | W1_r]
// BM=128, BN=128, BK=32; 256 threads (8 warps: 4 in M x 2 in N).
// Each warp: 32x64 tile = 2 (M) x 8 (N) mma.m16n8k8 tiles per k-step.
// ---------------------------------------------------------------------------
__global__ __launch_bounds__(256) void gemm1_tc_kernel(
    const float* __restrict__ x, int n_nodes)
{
    __shared__ unsigned As[128 * 36];   // [m][k], pitch 36
    __shared__ unsigned Bs[32 * 132];   // [k][n], pitch 132

    const int tid   = threadIdx.x;
    const int lane  = tid & 31;
    const int warp  = tid >> 5;
    const int warpM = warp & 3;         // 0..3
    const int warpN = warp >> 2;        // 0..1
    const int g     = lane >> 2;        // groupID 0..7
    const int tig   = lane & 3;         // 0..3
    const int m0    = blockIdx.x * 128;

    float acc[2][8][4];
#pragma unroll
    for (int a = 0; a < 2; a++)
#pragma unroll
        for (int b = 0; b < 8; b++)
#pragma unroll
            for (int c = 0; c < 4; c++) acc[a][b][c] = 0.0f;

    // A staging mapping: each thread loads one row's 16 cols (4 x float4)
    const int arow = tid >> 1;               // 0..127
    const int acol = (tid & 1) * 16;         // 0 or 16
    const bool rowok = (m0 + arow) < n_nodes;
    const float* xrow = x + (size_t)(m0 + arow) * DIN;

    for (int kb = 0; kb < DIN / 32; kb++) {
        // --- stage A tile (128 x 32), cvt to tf32 ---
#pragma unroll
        for (int j = 0; j < 4; j++) {
            float4 v = make_float4(0.f, 0.f, 0.f, 0.f);
            if (rowok)
                v = *reinterpret_cast<const float4*>(xrow + kb * 32 + acol + j * 4);
            uint4 u = make_uint4(f2tf32(v.x), f2tf32(v.y), f2tf32(v.z), f2tf32(v.w));
            *reinterpret_cast<uint4*>(&As[arow * 36 + acol + j * 4]) = u;
        }
        // --- stage B tile (32 x 128) from pre-converted g_Btf ---
        {
            const uint4* srcb = reinterpret_cast<const uint4*>(&g_Btf[kb * 32 * 128]);
#pragma unroll
            for (int j = 0; j < 4; j++) {
                int lin = tid + j * 256;          // uint4 index, 0..1023
                int k   = lin >> 5;               // 32 uint4 per row
                int n4  = lin & 31;
                uint4 v = srcb[lin];
                *reinterpret_cast<uint4*>(&Bs[k * 132 + n4 * 4]) = v;
            }
        }
        __syncthreads();

#pragma unroll
        for (int ss = 0; ss < 4; ss++) {
            const int k0 = ss * 8;
            // B fragments: b0 = B[k0+tig][n], b1 = B[k0+tig+4][n], n = warpN*64 + t*8 + g
            unsigned br[16];
#pragma unroll
            for (int t = 0; t < 8; t++) {
                int n = warpN * 64 + t * 8 + g;
                br[t * 2 + 0] = Bs[(k0 + tig) * 132 + n];
                br[t * 2 + 1] = Bs[(k0 + tig + 4) * 132 + n];
            }
#pragma unroll
            for (int m2 = 0; m2 < 2; m2++) {
                int R = warpM * 32 + m2 * 16 + g;
                unsigned a0 = As[R * 36 + k0 + tig];
                unsigned a1 = As[(R + 8) * 36 + k0 + tig];
                unsigned a2 = As[R * 36 + k0 + tig + 4];
                unsigned a3 = As[(R + 8) * 36 + k0 + tig + 4];
#pragma unroll
                for (int t = 0; t < 8; t++) {
                    asm volatile(
                        "mma.sync.aligned.m16n8k8.row.col.f32.tf32.tf32.f32 "
                        "{%0,%1,%2,%3}, {%4,%5,%6,%7}, {%8,%9}, {%0,%1,%2,%3};\n"
                        : "+f"(acc[m2][t][0]), "+f"(acc[m2][t][1]),
                          "+f"(acc[m2][t][2]), "+f"(acc[m2][t][3])
                        : "r"(a0), "r"(a1), "r"(a2), "r"(a3),
                          "r"(br[t * 2]), "r"(br[t * 2 + 1]));
                }
            }
        }
        __syncthreads();
    }

    // Store: warpN==0 -> g_yl, warpN==1 -> g_yr. Cols tig*2, tig*2+1 adjacent.
    float* outbase = (warpN == 0) ? g_yl : g_yr;
#pragma unroll
    for (int m2 = 0; m2 < 2; m2++) {
        int R0 = m0 + warpM * 32 + m2 * 16 + g;
        int R1 = R0 + 8;
#pragma unroll
        for (int t = 0; t < 8; t++) {
            int nl = t * 8 + tig * 2;   // 0..63 within the half
            if (R0 < n_nodes)
                *reinterpret_cast<float2*>(&outbase[(size_t)R0 * DH + nl]) =
                    make_float2(acc[m2][t][0], acc[m2][t][1]);
            if (R1 < n_nodes)
                *reinterpret_cast<float2*>(&outbase[(size_t)R1 * DH + nl]) =
                    make_float2(acc[m2][t][2], acc[m2][t][3]);
        }
    }
}

// ---------------------------------------------------------------------------
// Scatter1: acc1[dst] += yl[src] (vector f32x4 reductions, 16 threads/edge)
// Also counts degree (one lane per edge).
// ---------------------------------------------------------------------------
__global__ void scatter1_kernel(const int* __restrict__ src,
                                const int* __restrict__ dst, int E) {
    int t = blockIdx.x * blockDim.x + threadIdx.x;
    int e = t >> 4;
    if (e >= E) return;
    int q = t & 15;
    int s = __ldg(&src[e]);
    int d = __ldg(&dst[e]);
    float4 v = *reinterpret_cast<const float4*>(&g_yl[(size_t)s * DH + q * 4]);
    asm volatile("red.global.add.v4.f32 [%0], {%1,%2,%3,%4};"
                 :: "l"(&g_acc1[(size_t)d * DH + q * 4]),
                    "f"(v.x), "f"(v.y), "f"(v.z), "f"(v.w) : "memory");
    if (q == 0) atomicAdd(&g_deg[d], 1.0f);
}

// ---------------------------------------------------------------------------
// Combine1 + layer-2 transform, fused:
//   out1 = acc1/max(deg,1) + b1 + yr ; h = relu(normalize(out1))
//   zl = h @ W2_l ; zr = h @ W2_r
// 256 threads = 4 nodes/block, 64 threads/node.
// ---------------------------------------------------------------------------
__global__ __launch_bounds__(256) void combine1_gemm2_kernel(
    const float* __restrict__ b1,
    const float* __restrict__ W2l,
    const float* __restrict__ W2r,
    int n_nodes)
{
    __shared__ float sW[DH * 8];
    __shared__ float sh[4][DH];
    __shared__ float swsum[4][2];

    int tid = threadIdx.x;
    for (int i = tid; i < DH * 8; i += 256) {
        int k = i >> 3, j = i & 7;
        sW[i] = (j < 4) ? W2l[k * DOUT + j] : W2r[k * DOUT + (j - 4)];
    }

    int nl = tid >> 6;
    int f  = tid & 63;
    int n  = blockIdx.x * 4 + nl;

    float val = 0.0f;
    if (n < n_nodes) {
        float d = fmaxf(g_deg[n], 1.0f);
        val = g_acc1[(size_t)n * DH + f] / d + b1[f] + g_yr[(size_t)n * DH + f];
    }
    float sq = val * val;
#pragma unroll
    for (int o = 16; o > 0; o >>= 1) sq += __shfl_xor_sync(0xffffffffu, sq, o);
    if ((tid & 31) == 0) swsum[nl][(f >> 5)] = sq;
    __syncthreads();

    float norm = sqrtf(swsum[nl][0] + swsum[nl][1]);
    float h = fmaxf(val / fmaxf(norm, 1e-12f), 0.0f);
    sh[nl][f] = h;
    __syncthreads();

    if (f < 8 && n < n_nodes) {
        float a = 0.0f;
#pragma unroll
        for (int k = 0; k < DH; k++) a = fmaf(sh[nl][k], sW[k * 8 + f], a);
        if (f < 4) g_zl[(size_t)n * DOUT + f]       = a;
        else       g_zr[(size_t)n * DOUT + (f - 4)] = a;
    }
}

// ---------------------------------------------------------------------------
// Scatter2: acc2[dst] += zl[src] (one f32x4 vector reduction per edge)
// ---------------------------------------------------------------------------
__global__ void scatter2_kernel(const int* __restrict__ src,
                                const int* __restrict__ dst, int E) {
    int e = blockIdx.x * blockDim.x + threadIdx.x;
    if (e >= E) return;
    int s = __ldg(&src[e]);
    int d = __ldg(&dst[e]);
    float4 v = *reinterpret_cast<const float4*>(&g_zl[(size_t)s * DOUT]);
    asm volatile("red.global.add.v4.f32 [%0], {%1,%2,%3,%4};"
                 :: "l"(&g_acc2[(size_t)d * DOUT]),
                    "f"(v.x), "f"(v.y), "f"(v.z), "f"(v.w) : "memory");
}

// ---------------------------------------------------------------------------
// Combine2: out = normalize(acc2/max(deg,1) + b2 + zr)
// ---------------------------------------------------------------------------
__global__ void combine2_kernel(const float* __restrict__ b2,
                                float* __restrict__ out, int n_nodes) {
    int n = blockIdx.x * blockDim.x + threadIdx.x;
    if (n >= n_nodes) return;
    float d = fmaxf(g_deg[n], 1.0f);
    float4 a = *reinterpret_cast<const float4*>(&g_acc2[n * DOUT]);
    float4 r = *reinterpret_cast<const float4*>(&g_zr[n * DOUT]);
    float v0 = a.x / d + b2[0] + r.x;
    float v1 = a.y / d + b2[1] + r.y;
    float v2 = a.z / d + b2[2] + r.z;
    float v3 = a.w / d + b2[3] + r.w;
    float norm = fmaxf(sqrtf(v0 * v0 + v1 * v1 + v2 * v2 + v3 * v3), 1e-12f);
    float4 o = make_float4(v0 / norm, v1 / norm, v2 / norm, v3 / norm);
    *reinterpret_cast<float4*>(&out[n * DOUT]) = o;
}

// ---------------------------------------------------------------------------
// Launch
// ---------------------------------------------------------------------------
extern "C" void kernel_launch(void* const* d_in, const int* in_sizes, int n_in,
                              void* d_out, int out_size) {
    const float* x   = (const float*)d_in[0];
    const int*   ei  = (const int*)  d_in[1];
    const float* W1l = (const float*)d_in[2];
    const float* b1  = (const float*)d_in[3];
    const float* W1r = (const float*)d_in[4];
    const float* W2l = (const float*)d_in[5];
    const float* b2  = (const float*)d_in[6];
    const float* W2r = (const float*)d_in[7];
    float* out = (float*)d_out;

    const int N = in_sizes[0] / DIN;     // 100000
    const int E = in_sizes[1] / 2;       // 320000
    const int* src = ei;
    const int* dst = ei + E;

    zero_kernel<<<(N * (DH / 4) + 255) / 256, 256>>>(N);
    btf_kernel<<<(DIN * 128 + 255) / 256, 256>>>(W1l, W1r);
    gemm1_tc_kernel<<<(N + 127) / 128, 256>>>(x, N);
    scatter1_kernel<<<((size_t)E * 16 + 255) / 256, 256>>>(src, dst, E);
    combine1_gemm2_kernel<<<(N + 3) / 4, 256>>>(b1, W2l, W2r, N);
    scatter2_kernel<<<(E + 255) / 256, 256>>>(src, dst, E);
    combine2_kernel<<<(N + 255) / 256, 256>>>(b2, out, N);
}

// round 9
// speedup vs baseline: 2.3018x; 1.2180x over previous
#include <cuda_runtime.h>
#include <cuda_fp16.h>
#include <cuda_bf16.h>
#include <cstdint>
#include <math.h>

#define NMAX   100000
#define DIN    256
#define DH     64
#define DOUT   4

// Scratch (static __device__ arrays -- no allocation allowed)
__device__ float g_yl[NMAX * DH];      // x @ W1_l
__device__ float g_yr[NMAX * DH];      // x @ W1_r
__device__ float g_acc1[NMAX * DH];    // edge-aggregated y_l
__device__ float g_deg[NMAX];          // in-degree (float)
__device__ float g_zl[NMAX * DOUT];    // h @ W2_l
__device__ float g_zr[NMAX * DOUT];    // h @ W2_r
__device__ float g_acc2[NMAX * DOUT];
__device__ uint4 g_Bh[128 * 32];       // f16 [W1_l | W1_r], [n][k] K-major, packed h2

__device__ __forceinline__ unsigned h2u(half2 h) {
    union { half2 h; unsigned u; } c;
    c.h = h;
    return c.u;
}

// ---------------------------------------------------------------------------
// Prep: zero accumulators/degree + convert B = [W1_l|W1_r]^T to f16 [n][k]
// ---------------------------------------------------------------------------
__global__ void prep_kernel(const float* __restrict__ Wl,
                            const float* __restrict__ Wr, int n_nodes) {
    int i = blockIdx.x * blockDim.x + threadIdx.x;
    float4 z = make_float4(0.f, 0.f, 0.f, 0.f);
    if (i < n_nodes * (DH / 4)) reinterpret_cast<float4*>(g_acc1)[i] = z;
    if (i < n_nodes)            reinterpret_cast<float4*>(g_acc2)[i] = z;
    if (i < n_nodes)            g_deg[i] = 0.0f;
    if (i < 128 * 32) {
        int n  = i >> 5;            // output col 0..127
        int k8 = (i & 31) * 8;      // k base
        const float* W = (n < DH) ? Wl : Wr;
        int col = (n < DH) ? n : (n - DH);
        unsigned u[4];
#pragma unroll
        for (int j = 0; j < 4; j++)
            u[j] = h2u(__floats2half2_rn(W[(k8 + 2 * j) * DH + col],
                                         W[(k8 + 2 * j + 1) * DH + col]));
        g_Bh[i] = make_uint4(u[0], u[1], u[2], u[3]);
    }
}

// ---------------------------------------------------------------------------
// GEMM1 (f16 legacy mma): y[N,128] = x[N,256] @ [W1_l | W1_r]
// 512 threads = 16 warps (4M x 4N), warp tile 32x32, CTA tile 128x128.
// B fully SMEM-resident; A double-buffered (BK=32).
// ---------------------------------------------------------------------------
#define APITCH 80                 // bytes per A row (32 f16 + 8 pad)
#define BPITCH 528                // bytes per B row (256 f16 + 8 pad)
#define SM_A0  0
#define SM_A1  10240
#define SM_B   20480
#define SM_TOT (20480 + 128 * BPITCH)   // 88064

__device__ __forceinline__ uint32_t smem_u32(const void* p) {
    uint32_t a;
    asm("{ .reg .u64 t; cvta.to.shared.u64 t, %1; cvt.u32.u64 %0, t; }" : "=r"(a) : "l"(p));
    return a;
}

__global__ __launch_bounds__(512) void gemm1_f16_kernel(
    const float* __restrict__ x, int n_nodes)
{
    extern __shared__ char smem[];
    const uint32_t sb = smem_u32(smem);
    const int tid   = threadIdx.x;
    const int lane  = tid & 31;
    const int wid   = tid >> 5;
    const int warpM = wid & 3;            // 0..3
    const int warpN = wid >> 2;           // 0..3
    const int g     = lane >> 2;          // 0..7
    const int tig   = lane & 3;           // 0..3
    const int m0    = blockIdx.x * 128;

    // ---- load entire B (128x256 f16) into smem once ----
    {
        const uint4* src = g_Bh;
#pragma unroll
        for (int j = 0; j < 8; j++) {
            int idx = tid + j * 512;          // 0..4095
            int n   = idx >> 5;
            int k16 = idx & 31;
            *reinterpret_cast<uint4*>(smem + SM_B + n * BPITCH + k16 * 16) = src[idx];
        }
    }

    float acc[2][4][4];
#pragma unroll
    for (int a = 0; a < 2; a++)
#pragma unroll
        for (int b = 0; b < 4; b++)
#pragma unroll
            for (int c = 0; c < 4; c++) acc[a][b][c] = 0.0f;

    // A staging: thread -> row = tid/4, kc = (tid%4)*8
    const int arow = tid >> 2;
    const int kc   = (tid & 3) * 8;
    const bool rowok = (m0 + arow) < n_nodes;
    const float* xrow = x + (size_t)(m0 + arow) * DIN + kc;

    float4 s0, s1;
    auto load_regs = [&](int kb) {
        s0 = make_float4(0.f, 0.f, 0.f, 0.f);
        s1 = s0;
        if (rowok) {
            s0 = *reinterpret_cast<const float4*>(xrow + kb * 32);
            s1 = *reinterpret_cast<const float4*>(xrow + kb * 32 + 4);
        }
    };
    auto store_smem = [&](int buf) {
        uint4 u = make_uint4(h2u(__floats2half2_rn(s0.x, s0.y)),
                             h2u(__floats2half2_rn(s0.z, s0.w)),
                             h2u(__floats2half2_rn(s1.x, s1.y)),
                             h2u(__floats2half2_rn(s1.z, s1.w)));
        *reinterpret_cast<uint4*>(smem + (buf ? SM_A1 : SM_A0) +
                                  arow * APITCH + kc * 2) = u;
    };

    load_regs(0);
    store_smem(0);
    __syncthreads();

    for (int kb = 0; kb < 8; kb++) {
        if (kb < 7) load_regs(kb + 1);

        const uint32_t abase = sb + (kb & 1 ? SM_A1 : SM_A0);
#pragma unroll
        for (int ks2 = 0; ks2 < 2; ks2++) {
            const int ks = kb * 2 + ks2;
            // A fragments via ldmatrix.x4 (2 m-tiles)
            uint32_t af[2][4];
#pragma unroll
            for (int mt = 0; mt < 2; mt++) {
                uint32_t aptr = abase +
                    (warpM * 32 + mt * 16 + (lane & 15)) * APITCH +
                    (lane >> 4) * 16 + ks2 * 32;
                asm volatile(
                    "ldmatrix.sync.aligned.m8n8.x4.shared.b16 {%0,%1,%2,%3}, [%4];"
                    : "=r"(af[mt][0]), "=r"(af[mt][1]),
                      "=r"(af[mt][2]), "=r"(af[mt][3]) : "r"(aptr));
            }
            // B fragments (4 n-tiles), scalar 32-bit LDS, conflict-free
            uint32_t bf[4][2];
#pragma unroll
            for (int t = 0; t < 4; t++) {
                uint32_t bptr = sb + SM_B +
                    (warpN * 32 + t * 8 + g) * BPITCH + ks * 32 + tig * 4;
                asm volatile("ld.shared.b32 %0, [%1];" : "=r"(bf[t][0]) : "r"(bptr));
                asm volatile("ld.shared.b32 %0, [%1];" : "=r"(bf[t][1]) : "r"(bptr + 16));
            }
#pragma unroll
            for (int mt = 0; mt < 2; mt++)
#pragma unroll
                for (int t = 0; t < 4; t++) {
                    asm volatile(
                        "mma.sync.aligned.m16n8k16.row.col.f32.f16.f16.f32 "
                        "{%0,%1,%2,%3}, {%4,%5,%6,%7}, {%8,%9}, {%0,%1,%2,%3};"
                        : "+f"(acc[mt][t][0]), "+f"(acc[mt][t][1]),
                          "+f"(acc[mt][t][2]), "+f"(acc[mt][t][3])
                        : "r"(af[mt][0]), "r"(af[mt][1]),
                          "r"(af[mt][2]), "r"(af[mt][3]),
                          "r"(bf[t][0]), "r"(bf[t][1]));
                }
        }
        if (kb < 7) {
            store_smem((kb + 1) & 1);
            __syncthreads();
        }
    }

    // Epilogue: cols 0-63 -> yl, 64-127 -> yr
    float* outb = (warpN < 2) ? g_yl : g_yr;
    const int colb = (warpN & 1) * 32 + tig * 2;
#pragma unroll
    for (int mt = 0; mt < 2; mt++) {
        int r0 = m0 + warpM * 32 + mt * 16 + g;
        int r1 = r0 + 8;
#pragma unroll
        for (int t = 0; t < 4; t++) {
            int col = colb + t * 8;
            if (r0 < n_nodes)
                *reinterpret_cast<float2*>(&outb[(size_t)r0 * DH + col]) =
                    make_float2(acc[mt][t][0], acc[mt][t][1]);
            if (r1 < n_nodes)
                *reinterpret_cast<float2*>(&outb[(size_t)r1 * DH + col]) =
                    make_float2(acc[mt][t][2], acc[mt][t][3]);
        }
    }
}

// ---------------------------------------------------------------------------
// Scatter1: acc1[dst] += yl[src] (16 threads/edge, red.v4) + degree
// (measured at REDG-throughput floor ~25us)
// ---------------------------------------------------------------------------
__global__ void scatter1_kernel(const int* __restrict__ src,
                                const int* __restrict__ dst, int E) {
    int t = blockIdx.x * blockDim.x + threadIdx.x;
    int e = t >> 4;
    if (e >= E) return;
    int q = t & 15;
    int s = __ldg(&src[e]);
    int d = __ldg(&dst[e]);
    float4 v = *reinterpret_cast<const float4*>(&g_yl[(size_t)s * DH + q * 4]);
    asm volatile("red.global.add.v4.f32 [%0], {%1,%2,%3,%4};"
                 :: "l"(&g_acc1[(size_t)d * DH + q * 4]),
                    "f"(v.x), "f"(v.y), "f"(v.z), "f"(v.w) : "memory");
    if (q == 0) atomicAdd(&g_deg[d], 1.0f);
}

// ---------------------------------------------------------------------------
// Combine1 + layer-2 transform, fused
// ---------------------------------------------------------------------------
__global__ __launch_bounds__(256) void combine1_gemm2_kernel(
    const float* __restrict__ b1,
    const float* __restrict__ W2l,
    const float* __restrict__ W2r,
    int n_nodes)
{
    __shared__ float sW[DH * 8];
    __shared__ float sh[4][DH];
    __shared__ float swsum[4][2];

    int tid = threadIdx.x;
    for (int i = tid; i < DH * 8; i += 256) {
        int k = i >> 3, j = i & 7;
        sW[i] = (j < 4) ? W2l[k * DOUT + j] : W2r[k * DOUT + (j - 4)];
    }

    int nl = tid >> 6;
    int f  = tid & 63;
    int n  = blockIdx.x * 4 + nl;

    float val = 0.0f;
    if (n < n_nodes) {
        float d = fmaxf(g_deg[n], 1.0f);
        val = g_acc1[(size_t)n * DH + f] / d + b1[f] + g_yr[(size_t)n * DH + f];
    }
    float sq = val * val;
#pragma unroll
    for (int o = 16; o > 0; o >>= 1) sq += __shfl_xor_sync(0xffffffffu, sq, o);
    if ((tid & 31) == 0) swsum[nl][(f >> 5)] = sq;
    __syncthreads();

    float norm = sqrtf(swsum[nl][0] + swsum[nl][1]);
    float h = fmaxf(val / fmaxf(norm, 1e-12f), 0.0f);
    sh[nl][f] = h;
    __syncthreads();

    if (f < 8 && n < n_nodes) {
        float a = 0.0f;
#pragma unroll
        for (int k = 0; k < DH; k++) a = fmaf(sh[nl][k], sW[k * 8 + f], a);
        if (f < 4) g_zl[(size_t)n * DOUT + f]       = a;
        else       g_zr[(size_t)n * DOUT + (f - 4)] = a;
    }
}

// ---------------------------------------------------------------------------
// Scatter2: acc2[dst] += zl[src]
// ---------------------------------------------------------------------------
__global__ void scatter2_kernel(const int* __restrict__ src,
                                const int* __restrict__ dst, int E) {
    int e = blockIdx.x * blockDim.x + threadIdx.x;
    if (e >= E) return;
    int s = __ldg(&src[e]);
    int d = __ldg(&dst[e]);
    float4 v = *reinterpret_cast<const float4*>(&g_zl[(size_t)s * DOUT]);
    asm volatile("red.global.add.v4.f32 [%0], {%1,%2,%3,%4};"
                 :: "l"(&g_acc2[(size_t)d * DOUT]),
                    "f"(v.x), "f"(v.y), "f"(v.z), "f"(v.w) : "memory");
}

// ---------------------------------------------------------------------------
// Combine2: out = normalize(acc2/max(deg,1) + b2 + zr)
// ---------------------------------------------------------------------------
__global__ void combine2_kernel(const float* __restrict__ b2,
                                float* __restrict__ out, int n_nodes) {
    int n = blockIdx.x * blockDim.x + threadIdx.x;
    if (n >= n_nodes) return;
    float d = fmaxf(g_deg[n], 1.0f);
    float4 a = *reinterpret_cast<const float4*>(&g_acc2[n * DOUT]);
    float4 r = *reinterpret_cast<const float4*>(&g_zr[n * DOUT]);
    float v0 = a.x / d + b2[0] + r.x;
    float v1 = a.y / d + b2[1] + r.y;
    float v2 = a.z / d + b2[2] + r.z;
    float v3 = a.w / d + b2[3] + r.w;
    float norm = fmaxf(sqrtf(v0 * v0 + v1 * v1 + v2 * v2 + v3 * v3), 1e-12f);
    *reinterpret_cast<float4*>(&out[n * DOUT]) =
        make_float4(v0 / norm, v1 / norm, v2 / norm, v3 / norm);
}

// ---------------------------------------------------------------------------
// Launch
// ---------------------------------------------------------------------------
extern "C" void kernel_launch(void* const* d_in, const int* in_sizes, int n_in,
                              void* d_out, int out_size) {
    const float* x   = (const float*)d_in[0];
    const int*   ei  = (const int*)  d_in[1];
    const float* W1l = (const float*)d_in[2];
    const float* b1  = (const float*)d_in[3];
    const float* W1r = (const float*)d_in[4];
    const float* W2l = (const float*)d_in[5];
    const float* b2  = (const float*)d_in[6];
    const float* W2r = (const float*)d_in[7];
    float* out = (float*)d_out;

    const int N = in_sizes[0] / DIN;     // 100000
    const int E = in_sizes[1] / 2;       // 320000
    const int* src = ei;
    const int* dst = ei + E;

    cudaFuncSetAttribute(gemm1_f16_kernel,
                         cudaFuncAttributeMaxDynamicSharedMemorySize, SM_TOT);

    prep_kernel<<<(N * (DH / 4) + 255) / 256, 256>>>(W1l, W1r, N);
    gemm1_f16_kernel<<<(N + 127) / 128, 512, SM_TOT>>>(x, N);
    scatter1_kernel<<<((size_t)E * 16 + 255) / 256, 256>>>(src, dst, E);
    combine1_gemm2_kernel<<<(N + 3) / 4, 256>>>(b1, W2l, W2r, N);
    scatter2_kernel<<<(E + 255) / 256, 256>>>(src, dst, E);
    combine2_kernel<<<(N + 255) / 256, 256>>>(b2, out, N);
}

// round 14
// speedup vs baseline: 2.7794x; 1.2075x over previous
#include <cuda_runtime.h>
#include <cuda_fp16.h>
#include <cuda_bf16.h>
#include <cstdint>
#include <math.h>

#define NMAX   100000
#define DIN    256
#define DH     64
#define DOUT   4

// Scratch (static __device__ arrays -- no allocation allowed)
__device__ float g_yl[NMAX * DH];      // x @ W1_l
__device__ float g_yr[NMAX * DH];      // x @ W1_r
__device__ float g_acc1[NMAX * DH];    // edge-aggregated y_l
__device__ float g_deg[NMAX];          // in-degree (float)
__device__ float g_zl[NMAX * DOUT];    // h @ W2_l
__device__ float g_zr[NMAX * DOUT];    // h @ W2_r
__device__ float g_acc2[NMAX * DOUT];
__device__ uint4 g_Bh[128 * 32];       // f16 [W1_l | W1_r], [n][k] K-major, packed h2

__device__ __forceinline__ unsigned h2u(half2 h) {
    union { half2 h; unsigned u; } c;
    c.h = h;
    return c.u;
}

// ---------------------------------------------------------------------------
// Prep: zero accumulators/degree + convert B = [W1_l|W1_r]^T to f16 [n][k]
// ---------------------------------------------------------------------------
__global__ void prep_kernel(const float* __restrict__ Wl,
                            const float* __restrict__ Wr, int n_nodes) {
    int i = blockIdx.x * blockDim.x + threadIdx.x;
    float4 z = make_float4(0.f, 0.f, 0.f, 0.f);
    if (i < n_nodes * (DH / 4)) reinterpret_cast<float4*>(g_acc1)[i] = z;
    if (i < n_nodes)            reinterpret_cast<float4*>(g_acc2)[i] = z;
    if (i < n_nodes)            g_deg[i] = 0.0f;
    if (i < 128 * 32) {
        int n  = i >> 5;            // output col 0..127
        int k8 = (i & 31) * 8;      // k base
        const float* W = (n < DH) ? Wl : Wr;
        int col = (n < DH) ? n : (n - DH);
        unsigned u[4];
#pragma unroll
        for (int j = 0; j < 4; j++)
            u[j] = h2u(__floats2half2_rn(W[(k8 + 2 * j) * DH + col],
                                         W[(k8 + 2 * j + 1) * DH + col]));
        g_Bh[i] = make_uint4(u[0], u[1], u[2], u[3]);
    }
}

// ---------------------------------------------------------------------------
// GEMM1 (f16 legacy mma): y[N,128] = x[N,256] @ [W1_l | W1_r]
// 512 threads = 16 warps (4M x 4N), warp tile 32x32, CTA tile 128x128.
// B fully SMEM-resident; A double-buffered (BK=32).
// ---------------------------------------------------------------------------
#define APITCH 80                 // bytes per A row (32 f16 + 8 pad)
#define BPITCH 528                // bytes per B row (256 f16 + 8 pad)
#define SM_A0  0
#define SM_A1  10240
#define SM_B   20480
#define SM_TOT (20480 + 128 * BPITCH)   // 88064

__device__ __forceinline__ uint32_t smem_u32(const void* p) {
    uint32_t a;
    asm("{ .reg .u64 t; cvta.to.shared.u64 t, %1; cvt.u32.u64 %0, t; }" : "=r"(a) : "l"(p));
    return a;
}

__global__ __launch_bounds__(512) void gemm1_f16_kernel(
    const float* __restrict__ x, int n_nodes)
{
    extern __shared__ char smem[];
    const uint32_t sb = smem_u32(smem);
    const int tid   = threadIdx.x;
    const int lane  = tid & 31;
    const int wid   = tid >> 5;
    const int warpM = wid & 3;            // 0..3
    const int warpN = wid >> 2;           // 0..3
    const int g     = lane >> 2;          // 0..7
    const int tig   = lane & 3;           // 0..3
    const int m0    = blockIdx.x * 128;

    // ---- load entire B (128x256 f16) into smem once ----
    {
        const uint4* src = g_Bh;
#pragma unroll
        for (int j = 0; j < 8; j++) {
            int idx = tid + j * 512;          // 0..4095
            int n   = idx >> 5;
            int k16 = idx & 31;
            *reinterpret_cast<uint4*>(smem + SM_B + n * BPITCH + k16 * 16) = src[idx];
        }
    }

    float acc[2][4][4];
#pragma unroll
    for (int a = 0; a < 2; a++)
#pragma unroll
        for (int b = 0; b < 4; b++)
#pragma unroll
            for (int c = 0; c < 4; c++) acc[a][b][c] = 0.0f;

    // A staging: thread -> row = tid/4, kc = (tid%4)*8
    const int arow = tid >> 2;
    const int kc   = (tid & 3) * 8;
    const bool rowok = (m0 + arow) < n_nodes;
    const float* xrow = x + (size_t)(m0 + arow) * DIN + kc;

    float4 s0, s1;
    auto load_regs = [&](int kb) {
        s0 = make_float4(0.f, 0.f, 0.f, 0.f);
        s1 = s0;
        if (rowok) {
            s0 = *reinterpret_cast<const float4*>(xrow + kb * 32);
            s1 = *reinterpret_cast<const float4*>(xrow + kb * 32 + 4);
        }
    };
    auto store_smem = [&](int buf) {
        uint4 u = make_uint4(h2u(__floats2half2_rn(s0.x, s0.y)),
                             h2u(__floats2half2_rn(s0.z, s0.w)),
                             h2u(__floats2half2_rn(s1.x, s1.y)),
                             h2u(__floats2half2_rn(s1.z, s1.w)));
        *reinterpret_cast<uint4*>(smem + (buf ? SM_A1 : SM_A0) +
                                  arow * APITCH + kc * 2) = u;
    };

    load_regs(0);
    store_smem(0);
    __syncthreads();

    for (int kb = 0; kb < 8; kb++) {
        if (kb < 7) load_regs(kb + 1);

        const uint32_t abase = sb + (kb & 1 ? SM_A1 : SM_A0);
#pragma unroll
        for (int ks2 = 0; ks2 < 2; ks2++) {
            const int ks = kb * 2 + ks2;
            // A fragments via ldmatrix.x4 (2 m-tiles)
            uint32_t af[2][4];
#pragma unroll
            for (int mt = 0; mt < 2; mt++) {
                uint32_t aptr = abase +
                    (warpM * 32 + mt * 16 + (lane & 15)) * APITCH +
                    (lane >> 4) * 16 + ks2 * 32;
                asm volatile(
                    "ldmatrix.sync.aligned.m8n8.x4.shared.b16 {%0,%1,%2,%3}, [%4];"
                    : "=r"(af[mt][0]), "=r"(af[mt][1]),
                      "=r"(af[mt][2]), "=r"(af[mt][3]) : "r"(aptr));
            }
            // B fragments (4 n-tiles), scalar 32-bit LDS, conflict-free
            uint32_t bf[4][2];
#pragma unroll
            for (int t = 0; t < 4; t++) {
                uint32_t bptr = sb + SM_B +
                    (warpN * 32 + t * 8 + g) * BPITCH + ks * 32 + tig * 4;
                asm volatile("ld.shared.b32 %0, [%1];" : "=r"(bf[t][0]) : "r"(bptr));
                asm volatile("ld.shared.b32 %0, [%1];" : "=r"(bf[t][1]) : "r"(bptr + 16));
            }
#pragma unroll
            for (int mt = 0; mt < 2; mt++)
#pragma unroll
                for (int t = 0; t < 4; t++) {
                    asm volatile(
                        "mma.sync.aligned.m16n8k16.row.col.f32.f16.f16.f32 "
                        "{%0,%1,%2,%3}, {%4,%5,%6,%7}, {%8,%9}, {%0,%1,%2,%3};"
                        : "+f"(acc[mt][t][0]), "+f"(acc[mt][t][1]),
                          "+f"(acc[mt][t][2]), "+f"(acc[mt][t][3])
                        : "r"(af[mt][0]), "r"(af[mt][1]),
                          "r"(af[mt][2]), "r"(af[mt][3]),
                          "r"(bf[t][0]), "r"(bf[t][1]));
                }
        }
        if (kb < 7) {
            store_smem((kb + 1) & 1);
            __syncthreads();
        }
    }

    // Epilogue: cols 0-63 -> yl, 64-127 -> yr
    float* outb = (warpN < 2) ? g_yl : g_yr;
    const int colb = (warpN & 1) * 32 + tig * 2;
#pragma unroll
    for (int mt = 0; mt < 2; mt++) {
        int r0 = m0 + warpM * 32 + mt * 16 + g;
        int r1 = r0 + 8;
#pragma unroll
        for (int t = 0; t < 4; t++) {
            int col = colb + t * 8;
            if (r0 < n_nodes)
                *reinterpret_cast<float2*>(&outb[(size_t)r0 * DH + col]) =
                    make_float2(acc[mt][t][0], acc[mt][t][1]);
            if (r1 < n_nodes)
                *reinterpret_cast<float2*>(&outb[(size_t)r1 * DH + col]) =
                    make_float2(acc[mt][t][2], acc[mt][t][3]);
        }
    }
}

// ---------------------------------------------------------------------------
// Scatter1: acc1[dst] += yl[src] (16 threads/edge, red.v4) + degree
// ---------------------------------------------------------------------------
__global__ void scatter1_kernel(const int* __restrict__ src,
                                const int* __restrict__ dst, int E) {
    int t = blockIdx.x * blockDim.x + threadIdx.x;
    int e = t >> 4;
    if (e >= E) return;
    int q = t & 15;
    int s = __ldg(&src[e]);
    int d = __ldg(&dst[e]);
    float4 v = *reinterpret_cast<const float4*>(&g_yl[(size_t)s * DH + q * 4]);
    asm volatile("red.global.add.v4.f32 [%0], {%1,%2,%3,%4};"
                 :: "l"(&g_acc1[(size_t)d * DH + q * 4]),
                    "f"(v.x), "f"(v.y), "f"(v.z), "f"(v.w) : "memory");
    if (q == 0) atomicAdd(&g_deg[d], 1.0f);
}

// ---------------------------------------------------------------------------
// Combine1 + layer-2 transform, warp-per-node, register-resident W2:
//   out1 = acc1/max(deg,1) + b1 + yr ; h = relu(normalize(out1))
//   zl = h @ W2_l ; zr = h @ W2_r
// ---------------------------------------------------------------------------
__global__ __launch_bounds__(256) void combine1_gemm2_kernel(
    const float* __restrict__ b1,
    const float* __restrict__ W2l,
    const float* __restrict__ W2r,
    int n_nodes)
{
    const int tid  = threadIdx.x;
    const int lane = tid & 31;
    const int w    = tid >> 5;
    const int k0   = lane * 2;          // this thread's two feature rows

    // preload W2 rows k0, k0+1 (8 outputs each) into registers
    float wreg[2][8];
#pragma unroll
    for (int r = 0; r < 2; r++) {
        int k = k0 + r;
#pragma unroll
        for (int j = 0; j < 8; j++)
            wreg[r][j] = (j < 4) ? __ldg(&W2l[k * DOUT + j])
                                 : __ldg(&W2r[k * DOUT + (j - 4)]);
    }
    const float b0 = __ldg(&b1[k0]);
    const float b1v = __ldg(&b1[k0 + 1]);

    const int warps_total = gridDim.x * 8;
    for (int n = blockIdx.x * 8 + w; n < n_nodes; n += warps_total) {
        float invd = 1.0f / fmaxf(g_deg[n], 1.0f);
        float2 a = *reinterpret_cast<const float2*>(&g_acc1[(size_t)n * DH + k0]);
        float2 r = *reinterpret_cast<const float2*>(&g_yr[(size_t)n * DH + k0]);
        float v0 = fmaf(a.x, invd, b0 + r.x);
        float v1 = fmaf(a.y, invd, b1v + r.y);

        float sq = v0 * v0 + v1 * v1;
#pragma unroll
        for (int o = 16; o > 0; o >>= 1) sq += __shfl_xor_sync(0xffffffffu, sq, o);
        float innorm = 1.0f / fmaxf(sqrtf(sq), 1e-12f);
        float h0 = fmaxf(v0 * innorm, 0.0f);
        float h1 = fmaxf(v1 * innorm, 0.0f);

        float p[8];
#pragma unroll
        for (int j = 0; j < 8; j++)
            p[j] = fmaf(h0, wreg[0][j], h1 * wreg[1][j]);
#pragma unroll
        for (int j = 0; j < 8; j++)
#pragma unroll
            for (int o = 16; o > 0; o >>= 1)
                p[j] += __shfl_xor_sync(0xffffffffu, p[j], o);

        if (lane == 0) {
            *reinterpret_cast<float4*>(&g_zl[(size_t)n * DOUT]) =
                make_float4(p[0], p[1], p[2], p[3]);
            *reinterpret_cast<float4*>(&g_zr[(size_t)n * DOUT]) =
                make_float4(p[4], p[5], p[6], p[7]);
        }
    }
}

// ---------------------------------------------------------------------------
// Scatter2: acc2[dst] += zl[src]
// ---------------------------------------------------------------------------
__global__ void scatter2_kernel(const int* __restrict__ src,
                                const int* __restrict__ dst, int E) {
    int e = blockIdx.x * blockDim.x + threadIdx.x;
    if (e >= E) return;
    int s = __ldg(&src[e]);
    int d = __ldg(&dst[e]);
    float4 v = *reinterpret_cast<const float4*>(&g_zl[(size_t)s * DOUT]);
    asm volatile("red.global.add.v4.f32 [%0], {%1,%2,%3,%4};"
                 :: "l"(&g_acc2[(size_t)d * DOUT]),
                    "f"(v.x), "f"(v.y), "f"(v.z), "f"(v.w) : "memory");
}

// ---------------------------------------------------------------------------
// Combine2: out = normalize(acc2/max(deg,1) + b2 + zr)
// ---------------------------------------------------------------------------
__global__ void combine2_kernel(const float* __restrict__ b2,
                                float* __restrict__ out, int n_nodes) {
    int n = blockIdx.x * blockDim.x + threadIdx.x;
    if (n >= n_nodes) return;
    float d = fmaxf(g_deg[n], 1.0f);
    float4 a = *reinterpret_cast<const float4*>(&g_acc2[n * DOUT]);
    float4 r = *reinterpret_cast<const float4*>(&g_zr[n * DOUT]);
    float v0 = a.x / d + b2[0] + r.x;
    float v1 = a.y / d + b2[1] + r.y;
    float v2 = a.z / d + b2[2] + r.z;
    float v3 = a.w / d + b2[3] + r.w;
    float norm = fmaxf(sqrtf(v0 * v0 + v1 * v1 + v2 * v2 + v3 * v3), 1e-12f);
    *reinterpret_cast<float4*>(&out[n * DOUT]) =
        make_float4(v0 / norm, v1 / norm, v2 / norm, v3 / norm);
}

// ---------------------------------------------------------------------------
// Launch
// ---------------------------------------------------------------------------
extern "C" void kernel_launch(void* const* d_in, const int* in_sizes, int n_in,
                              void* d_out, int out_size) {
    const float* x   = (const float*)d_in[0];
    const int*   ei  = (const int*)  d_in[1];
    const float* W1l = (const float*)d_in[2];
    const float* b1  = (const float*)d_in[3];
    const float* W1r = (const float*)d_in[4];
    const float* W2l = (const float*)d_in[5];
    const float* b2  = (const float*)d_in[6];
    const float* W2r = (const float*)d_in[7];
    float* out = (float*)d_out;

    const int N = in_sizes[0] / DIN;     // 100000
    const int E = in_sizes[1] / 2;       // 320000
    const int* src = ei;
    const int* dst = ei + E;

    cudaFuncSetAttribute(gemm1_f16_kernel,
                         cudaFuncAttributeMaxDynamicSharedMemorySize, SM_TOT);

    prep_kernel<<<(N * (DH / 4) + 255) / 256, 256>>>(W1l, W1r, N);
    gemm1_f16_kernel<<<(N + 127) / 128, 512, SM_TOT>>>(x, N);
    scatter1_kernel<<<((size_t)E * 16 + 255) / 256, 256>>>(src, dst, E);
    combine1_gemm2_kernel<<<1184, 256>>>(b1, W2l, W2r, N);   // 8 warps/block, ~3.4 nodes/warp
    scatter2_kernel<<<(E + 255) / 256, 256>>>(src, dst, E);
    combine2_kernel<<<(N + 255) / 256, 256>>>(b2, out, N);
}

// round 15
// speedup vs baseline: 3.0455x; 1.0957x over previous
#include <cuda_runtime.h>
#include <cuda_fp16.h>
#include <cuda_bf16.h>
#include <cstdint>
#include <math.h>

#define NMAX   100000
#define DIN    256
#define DH     64
#define DOUT   4

// Scratch (static __device__ arrays -- no allocation allowed)
__device__ float g_yl[NMAX * DH];      // x @ W1_l
__device__ float g_yr[NMAX * DH];      // x @ W1_r
__device__ float g_acc1[NMAX * DH];    // edge-aggregated y_l
__device__ float g_deg[NMAX];          // in-degree (float)
__device__ float g_zl[NMAX * DOUT];    // h @ W2_l
__device__ float g_zr[NMAX * DOUT];    // h @ W2_r
__device__ float g_acc2[NMAX * DOUT];
__device__ uint4 g_Bh[128 * 32];       // f16 [W1_l | W1_r], [n][k] K-major, packed h2

__device__ __forceinline__ unsigned h2u(half2 h) {
    union { half2 h; unsigned u; } c;
    c.h = h;
    return c.u;
}

// ---------------------------------------------------------------------------
// Prep: zero accumulators/degree + convert B = [W1_l|W1_r]^T to f16 [n][k]
// ---------------------------------------------------------------------------
__global__ void prep_kernel(const float* __restrict__ Wl,
                            const float* __restrict__ Wr, int n_nodes) {
    int i = blockIdx.x * blockDim.x + threadIdx.x;
    float4 z = make_float4(0.f, 0.f, 0.f, 0.f);
    if (i < n_nodes * (DH / 4)) reinterpret_cast<float4*>(g_acc1)[i] = z;
    if (i < n_nodes)            reinterpret_cast<float4*>(g_acc2)[i] = z;
    if (i < n_nodes)            g_deg[i] = 0.0f;
    if (i < 128 * 32) {
        int n  = i >> 5;            // output col 0..127
        int k8 = (i & 31) * 8;      // k base
        const float* W = (n < DH) ? Wl : Wr;
        int col = (n < DH) ? n : (n - DH);
        unsigned u[4];
#pragma unroll
        for (int j = 0; j < 4; j++)
            u[j] = h2u(__floats2half2_rn(W[(k8 + 2 * j) * DH + col],
                                         W[(k8 + 2 * j + 1) * DH + col]));
        g_Bh[i] = make_uint4(u[0], u[1], u[2], u[3]);
    }
}

// ---------------------------------------------------------------------------
// GEMM1 (f16 legacy mma): y[N,128] = x[N,256] @ [W1_l | W1_r]
// 512 threads = 16 warps (4M x 4N), warp tile 32x32, CTA tile 128x128.
// B fully SMEM-resident; A double-buffered (BK=32).
// ---------------------------------------------------------------------------
#define APITCH 80                 // bytes per A row (32 f16 + 8 pad)
#define BPITCH 528                // bytes per B row (256 f16 + 8 pad)
#define SM_A0  0
#define SM_A1  10240
#define SM_B   20480
#define SM_TOT (20480 + 128 * BPITCH)   // 88064

__device__ __forceinline__ uint32_t smem_u32(const void* p) {
    uint32_t a;
    asm("{ .reg .u64 t; cvta.to.shared.u64 t, %1; cvt.u32.u64 %0, t; }" : "=r"(a) : "l"(p));
    return a;
}

__global__ __launch_bounds__(512) void gemm1_f16_kernel(
    const float* __restrict__ x, int n_nodes)
{
    extern __shared__ char smem[];
    const uint32_t sb = smem_u32(smem);
    const int tid   = threadIdx.x;
    const int lane  = tid & 31;
    const int wid   = tid >> 5;
    const int warpM = wid & 3;            // 0..3
    const int warpN = wid >> 2;           // 0..3
    const int g     = lane >> 2;          // 0..7
    const int tig   = lane & 3;           // 0..3
    const int m0    = blockIdx.x * 128;

    // ---- load entire B (128x256 f16) into smem once ----
    {
        const uint4* src = g_Bh;
#pragma unroll
        for (int j = 0; j < 8; j++) {
            int idx = tid + j * 512;          // 0..4095
            int n   = idx >> 5;
            int k16 = idx & 31;
            *reinterpret_cast<uint4*>(smem + SM_B + n * BPITCH + k16 * 16) = src[idx];
        }
    }

    float acc[2][4][4];
#pragma unroll
    for (int a = 0; a < 2; a++)
#pragma unroll
        for (int b = 0; b < 4; b++)
#pragma unroll
            for (int c = 0; c < 4; c++) acc[a][b][c] = 0.0f;

    // A staging: thread -> row = tid/4, kc = (tid%4)*8
    const int arow = tid >> 2;
    const int kc   = (tid & 3) * 8;
    const bool rowok = (m0 + arow) < n_nodes;
    const float* xrow = x + (size_t)(m0 + arow) * DIN + kc;

    float4 s0, s1;
    auto load_regs = [&](int kb) {
        s0 = make_float4(0.f, 0.f, 0.f, 0.f);
        s1 = s0;
        if (rowok) {
            s0 = *reinterpret_cast<const float4*>(xrow + kb * 32);
            s1 = *reinterpret_cast<const float4*>(xrow + kb * 32 + 4);
        }
    };
    auto store_smem = [&](int buf) {
        uint4 u = make_uint4(h2u(__floats2half2_rn(s0.x, s0.y)),
                             h2u(__floats2half2_rn(s0.z, s0.w)),
                             h2u(__floats2half2_rn(s1.x, s1.y)),
                             h2u(__floats2half2_rn(s1.z, s1.w)));
        *reinterpret_cast<uint4*>(smem + (buf ? SM_A1 : SM_A0) +
                                  arow * APITCH + kc * 2) = u;
    };

    load_regs(0);
    store_smem(0);
    __syncthreads();

    for (int kb = 0; kb < 8; kb++) {
        if (kb < 7) load_regs(kb + 1);

        const uint32_t abase = sb + (kb & 1 ? SM_A1 : SM_A0);
#pragma unroll
        for (int ks2 = 0; ks2 < 2; ks2++) {
            const int ks = kb * 2 + ks2;
            // A fragments via ldmatrix.x4 (2 m-tiles)
            uint32_t af[2][4];
#pragma unroll
            for (int mt = 0; mt < 2; mt++) {
                uint32_t aptr = abase +
                    (warpM * 32 + mt * 16 + (lane & 15)) * APITCH +
                    (lane >> 4) * 16 + ks2 * 32;
                asm volatile(
                    "ldmatrix.sync.aligned.m8n8.x4.shared.b16 {%0,%1,%2,%3}, [%4];"
                    : "=r"(af[mt][0]), "=r"(af[mt][1]),
                      "=r"(af[mt][2]), "=r"(af[mt][3]) : "r"(aptr));
            }
            // B fragments (4 n-tiles), scalar 32-bit LDS, conflict-free
            uint32_t bf[4][2];
#pragma unroll
            for (int t = 0; t < 4; t++) {
                uint32_t bptr = sb + SM_B +
                    (warpN * 32 + t * 8 + g) * BPITCH + ks * 32 + tig * 4;
                asm volatile("ld.shared.b32 %0, [%1];" : "=r"(bf[t][0]) : "r"(bptr));
                asm volatile("ld.shared.b32 %0, [%1];" : "=r"(bf[t][1]) : "r"(bptr + 16));
            }
#pragma unroll
            for (int mt = 0; mt < 2; mt++)
#pragma unroll
                for (int t = 0; t < 4; t++) {
                    asm volatile(
                        "mma.sync.aligned.m16n8k16.row.col.f32.f16.f16.f32 "
                        "{%0,%1,%2,%3}, {%4,%5,%6,%7}, {%8,%9}, {%0,%1,%2,%3};"
                        : "+f"(acc[mt][t][0]), "+f"(acc[mt][t][1]),
                          "+f"(acc[mt][t][2]), "+f"(acc[mt][t][3])
                        : "r"(af[mt][0]), "r"(af[mt][1]),
                          "r"(af[mt][2]), "r"(af[mt][3]),
                          "r"(bf[t][0]), "r"(bf[t][1]));
                }
        }
        if (kb < 7) {
            store_smem((kb + 1) & 1);
            __syncthreads();
        }
    }

    // Epilogue: cols 0-63 -> yl, 64-127 -> yr
    float* outb = (warpN < 2) ? g_yl : g_yr;
    const int colb = (warpN & 1) * 32 + tig * 2;
#pragma unroll
    for (int mt = 0; mt < 2; mt++) {
        int r0 = m0 + warpM * 32 + mt * 16 + g;
        int r1 = r0 + 8;
#pragma unroll
        for (int t = 0; t < 4; t++) {
            int col = colb + t * 8;
            if (r0 < n_nodes)
                *reinterpret_cast<float2*>(&outb[(size_t)r0 * DH + col]) =
                    make_float2(acc[mt][t][0], acc[mt][t][1]);
            if (r1 < n_nodes)
                *reinterpret_cast<float2*>(&outb[(size_t)r1 * DH + col]) =
                    make_float2(acc[mt][t][2], acc[mt][t][3]);
        }
    }
}

// ---------------------------------------------------------------------------
// Scatter1: acc1[dst] += yl[src] (16 threads/edge, red.v4) + degree
// ---------------------------------------------------------------------------
__global__ void scatter1_kernel(const int* __restrict__ src,
                                const int* __restrict__ dst, int E) {
    int t = blockIdx.x * blockDim.x + threadIdx.x;
    int e = t >> 4;
    if (e >= E) return;
    int q = t & 15;
    int s = __ldg(&src[e]);
    int d = __ldg(&dst[e]);
    float4 v = *reinterpret_cast<const float4*>(&g_yl[(size_t)s * DH + q * 4]);
    asm volatile("red.global.add.v4.f32 [%0], {%1,%2,%3,%4};"
                 :: "l"(&g_acc1[(size_t)d * DH + q * 4]),
                    "f"(v.x), "f"(v.y), "f"(v.z), "f"(v.w) : "memory");
    if (q == 0) atomicAdd(&g_deg[d], 1.0f);
}

// ---------------------------------------------------------------------------
// Combine1 + layer-2 transform: warp-per-4-nodes, register W2, batched loads
// (MLP=12) and multi-value butterfly reduction (9 shfl for 8 outputs).
// ---------------------------------------------------------------------------
#define C1_BLOCKS 1184
__global__ __launch_bounds__(256) void combine1_gemm2_kernel(
    const float* __restrict__ b1,
    const float* __restrict__ W2l,
    const float* __restrict__ W2r,
    int n_nodes)
{
    const int tid  = threadIdx.x;
    const int lane = tid & 31;
    const int w    = tid >> 5;
    const int k0   = lane * 2;          // this thread's two feature rows

    // preload W2 rows k0, k0+1 (8 outputs each) into registers
    float wreg[2][8];
#pragma unroll
    for (int r = 0; r < 2; r++) {
        int k = k0 + r;
#pragma unroll
        for (int j = 0; j < 8; j++)
            wreg[r][j] = (j < 4) ? __ldg(&W2l[k * DOUT + j])
                                 : __ldg(&W2r[k * DOUT + (j - 4)]);
    }
    const float bb0 = __ldg(&b1[k0]);
    const float bb1 = __ldg(&b1[k0 + 1]);

    const bool hi16 = (lane & 16) != 0;
    const bool hi8  = (lane & 8)  != 0;
    const bool hi4  = (lane & 4)  != 0;

    const int warp_g = blockIdx.x * 8 + w;
    const int stride = C1_BLOCKS * 8 * 4;

    for (int nb = warp_g * 4; nb < n_nodes; nb += stride) {
        // ---- batched loads: 4 nodes, all issued before any compute ----
        float  dg[4];
        float2 a[4], r[4];
#pragma unroll
        for (int u = 0; u < 4; u++) {
            int n = nb + u;
            bool ok = n < n_nodes;
            int nc = ok ? n : nb;          // clamp (nb always valid)
            dg[u] = g_deg[nc];
            a[u] = *reinterpret_cast<const float2*>(&g_acc1[(size_t)nc * DH + k0]);
            r[u] = *reinterpret_cast<const float2*>(&g_yr[(size_t)nc * DH + k0]);
        }

#pragma unroll
        for (int u = 0; u < 4; u++) {
            int n = nb + u;
            if (n >= n_nodes) break;
            float invd = 1.0f / fmaxf(dg[u], 1.0f);
            float v0 = fmaf(a[u].x, invd, bb0 + r[u].x);
            float v1 = fmaf(a[u].y, invd, bb1 + r[u].y);

            float sq = v0 * v0 + v1 * v1;
#pragma unroll
            for (int o = 16; o > 0; o >>= 1)
                sq += __shfl_xor_sync(0xffffffffu, sq, o);
            float innorm = 1.0f / fmaxf(sqrtf(sq), 1e-12f);
            float h0 = fmaxf(v0 * innorm, 0.0f);
            float h1 = fmaxf(v1 * innorm, 0.0f);

            float p[8];
#pragma unroll
            for (int j = 0; j < 8; j++)
                p[j] = fmaf(h0, wreg[0][j], h1 * wreg[1][j]);

            // multi-value reduction: 8 values over 32 lanes in 9 shfls.
            // offset 16: keep 4 values (lo lanes j0..3, hi lanes j4..7)
            float q4[4];
#pragma unroll
            for (int i = 0; i < 4; i++) {
                float send = hi16 ? p[i] : p[i + 4];
                float rcv  = __shfl_xor_sync(0xffffffffu, send, 16);
                q4[i] = (hi16 ? p[i + 4] : p[i]) + rcv;
            }
            // offset 8: keep 2
            float q2[2];
#pragma unroll
            for (int i = 0; i < 2; i++) {
                float send = hi8 ? q4[i] : q4[i + 2];
                float rcv  = __shfl_xor_sync(0xffffffffu, send, 8);
                q2[i] = (hi8 ? q4[i + 2] : q4[i]) + rcv;
            }
            // offset 4: keep 1
            float s;
            {
                float send = hi4 ? q2[0] : q2[1];
                float rcv  = __shfl_xor_sync(0xffffffffu, send, 4);
                s = (hi4 ? q2[1] : q2[0]) + rcv;
            }
            // offsets 2, 1: scalar
            s += __shfl_xor_sync(0xffffffffu, s, 2);
            s += __shfl_xor_sync(0xffffffffu, s, 1);

            // lane 4j holds output j
            if ((lane & 3) == 0) {
                int j = lane >> 2;
                if (j < 4) g_zl[(size_t)n * DOUT + j]       = s;
                else       g_zr[(size_t)n * DOUT + (j - 4)] = s;
            }
        }
    }
}

// ---------------------------------------------------------------------------
// Scatter2: acc2[dst] += zl[src]
// ---------------------------------------------------------------------------
__global__ void scatter2_kernel(const int* __restrict__ src,
                                const int* __restrict__ dst, int E) {
    int e = blockIdx.x * blockDim.x + threadIdx.x;
    if (e >= E) return;
    int s = __ldg(&src[e]);
    int d = __ldg(&dst[e]);
    float4 v = *reinterpret_cast<const float4*>(&g_zl[(size_t)s * DOUT]);
    asm volatile("red.global.add.v4.f32 [%0], {%1,%2,%3,%4};"
                 :: "l"(&g_acc2[(size_t)d * DOUT]),
                    "f"(v.x), "f"(v.y), "f"(v.z), "f"(v.w) : "memory");
}

// ---------------------------------------------------------------------------
// Combine2: out = normalize(acc2/max(deg,1) + b2 + zr)
// ---------------------------------------------------------------------------
__global__ void combine2_kernel(const float* __restrict__ b2,
                                float* __restrict__ out, int n_nodes) {
    int n = blockIdx.x * blockDim.x + threadIdx.x;
    if (n >= n_nodes) return;
    float d = fmaxf(g_deg[n], 1.0f);
    float4 a = *reinterpret_cast<const float4*>(&g_acc2[n * DOUT]);
    float4 r = *reinterpret_cast<const float4*>(&g_zr[n * DOUT]);
    float v0 = a.x / d + b2[0] + r.x;
    float v1 = a.y / d + b2[1] + r.y;
    float v2 = a.z / d + b2[2] + r.z;
    float v3 = a.w / d + b2[3] + r.w;
    float norm = fmaxf(sqrtf(v0 * v0 + v1 * v1 + v2 * v2 + v3 * v3), 1e-12f);
    *reinterpret_cast<float4*>(&out[n * DOUT]) =
        make_float4(v0 / norm, v1 / norm, v2 / norm, v3 / norm);
}

// ---------------------------------------------------------------------------
// Launch
// ---------------------------------------------------------------------------
extern "C" void kernel_launch(void* const* d_in, const int* in_sizes, int n_in,
                              void* d_out, int out_size) {
    const float* x   = (const float*)d_in[0];
    const int*   ei  = (const int*)  d_in[1];
    const float* W1l = (const float*)d_in[2];
    const float* b1  = (const float*)d_in[3];
    const float* W1r = (const float*)d_in[4];
    const float* W2l = (const float*)d_in[5];
    const float* b2  = (const float*)d_in[6];
    const float* W2r = (const float*)d_in[7];
    float* out = (float*)d_out;

    const int N = in_sizes[0] / DIN;     // 100000
    const int E = in_sizes[1] / 2;       // 320000
    const int* src = ei;
    const int* dst = ei + E;

    cudaFuncSetAttribute(gemm1_f16_kernel,
                         cudaFuncAttributeMaxDynamicSharedMemorySize, SM_TOT);

    prep_kernel<<<(N * (DH / 4) + 255) / 256, 256>>>(W1l, W1r, N);
    gemm1_f16_kernel<<<(N + 127) / 128, 512, SM_TOT>>>(x, N);
    scatter1_kernel<<<((size_t)E * 16 + 255) / 256, 256>>>(src, dst, E);
    combine1_gemm2_kernel<<<C1_BLOCKS, 256>>>(b1, W2l, W2r, N);
    scatter2_kernel<<<(E + 255) / 256, 256>>>(src, dst, E);
    combine2_kernel<<<(N + 255) / 256, 256>>>(b2, out, N);
}

// round 16
// speedup vs baseline: 3.1163x; 1.0233x over previous
#include <cuda_runtime.h>
#include <cuda_fp16.h>
#include <cuda_bf16.h>
#include <cstdint>
#include <math.h>

#define NMAX   100000
#define DIN    256
#define DH     64
#define DOUT   4

// Scratch (static __device__ arrays -- no allocation allowed)
__device__ float g_yl[NMAX * DH];      // x @ W1_l
__device__ float g_yr[NMAX * DH];      // x @ W1_r
__device__ float g_acc1[NMAX * DH];    // edge-aggregated y_l
__device__ float g_deg[NMAX];          // in-degree (float)
__device__ float g_zl[NMAX * DOUT];    // h @ W2_l
__device__ float g_zr[NMAX * DOUT];    // h @ W2_r
__device__ float g_acc2[NMAX * DOUT];
__device__ uint4 g_Bh[128 * 32];       // f16 [W1_l | W1_r], [n][k] K-major, packed h2

__device__ __forceinline__ unsigned h2u(half2 h) {
    union { half2 h; unsigned u; } c;
    c.h = h;
    return c.u;
}

// ---------------------------------------------------------------------------
// Prep: zero accumulators/degree + convert B = [W1_l|W1_r]^T to f16 [n][k]
// ---------------------------------------------------------------------------
__global__ void prep_kernel(const float* __restrict__ Wl,
                            const float* __restrict__ Wr, int n_nodes) {
    int i = blockIdx.x * blockDim.x + threadIdx.x;
    float4 z = make_float4(0.f, 0.f, 0.f, 0.f);
    if (i < n_nodes * (DH / 4)) reinterpret_cast<float4*>(g_acc1)[i] = z;
    if (i < n_nodes)            reinterpret_cast<float4*>(g_acc2)[i] = z;
    if (i < n_nodes)            g_deg[i] = 0.0f;
    if (i < 128 * 32) {
        int n  = i >> 5;            // output col 0..127
        int k8 = (i & 31) * 8;      // k base
        const float* W = (n < DH) ? Wl : Wr;
        int col = (n < DH) ? n : (n - DH);
        unsigned u[4];
#pragma unroll
        for (int j = 0; j < 4; j++)
            u[j] = h2u(__floats2half2_rn(W[(k8 + 2 * j) * DH + col],
                                         W[(k8 + 2 * j + 1) * DH + col]));
        g_Bh[i] = make_uint4(u[0], u[1], u[2], u[3]);
    }
}

// ---------------------------------------------------------------------------
// GEMM1 (f16 legacy mma): y[N,128] = x[N,256] @ [W1_l | W1_r]
// 512 threads = 16 warps (4M x 4N), warp tile 32x32, CTA tile 128x128.
// B fully SMEM-resident; A double-buffered (BK=32).
// ---------------------------------------------------------------------------
#define APITCH 80                 // bytes per A row (32 f16 + 8 pad)
#define BPITCH 528                // bytes per B row (256 f16 + 8 pad)
#define SM_A0  0
#define SM_A1  10240
#define SM_B   20480
#define SM_TOT (20480 + 128 * BPITCH)   // 88064

__device__ __forceinline__ uint32_t smem_u32(const void* p) {
    uint32_t a;
    asm("{ .reg .u64 t; cvta.to.shared.u64 t, %1; cvt.u32.u64 %0, t; }" : "=r"(a) : "l"(p));
    return a;
}

__global__ __launch_bounds__(512) void gemm1_f16_kernel(
    const float* __restrict__ x, int n_nodes)
{
    extern __shared__ char smem[];
    const uint32_t sb = smem_u32(smem);
    const int tid   = threadIdx.x;
    const int lane  = tid & 31;
    const int wid   = tid >> 5;
    const int warpM = wid & 3;            // 0..3
    const int warpN = wid >> 2;           // 0..3
    const int g     = lane >> 2;          // 0..7
    const int tig   = lane & 3;           // 0..3
    const int m0    = blockIdx.x * 128;

    // ---- load entire B (128x256 f16) into smem once ----
    {
        const uint4* src = g_Bh;
#pragma unroll
        for (int j = 0; j < 8; j++) {
            int idx = tid + j * 512;          // 0..4095
            int n   = idx >> 5;
            int k16 = idx & 31;
            *reinterpret_cast<uint4*>(smem + SM_B + n * BPITCH + k16 * 16) = src[idx];
        }
    }

    float acc[2][4][4];
#pragma unroll
    for (int a = 0; a < 2; a++)
#pragma unroll
        for (int b = 0; b < 4; b++)
#pragma unroll
            for (int c = 0; c < 4; c++) acc[a][b][c] = 0.0f;

    // A staging: thread -> row = tid/4, kc = (tid%4)*8
    const int arow = tid >> 2;
    const int kc   = (tid & 3) * 8;
    const bool rowok = (m0 + arow) < n_nodes;
    const float* xrow = x + (size_t)(m0 + arow) * DIN + kc;

    float4 s0, s1;
    auto load_regs = [&](int kb) {
        s0 = make_float4(0.f, 0.f, 0.f, 0.f);
        s1 = s0;
        if (rowok) {
            s0 = *reinterpret_cast<const float4*>(xrow + kb * 32);
            s1 = *reinterpret_cast<const float4*>(xrow + kb * 32 + 4);
        }
    };
    auto store_smem = [&](int buf) {
        uint4 u = make_uint4(h2u(__floats2half2_rn(s0.x, s0.y)),
                             h2u(__floats2half2_rn(s0.z, s0.w)),
                             h2u(__floats2half2_rn(s1.x, s1.y)),
                             h2u(__floats2half2_rn(s1.z, s1.w)));
        *reinterpret_cast<uint4*>(smem + (buf ? SM_A1 : SM_A0) +
                                  arow * APITCH + kc * 2) = u;
    };

    load_regs(0);
    store_smem(0);
    __syncthreads();

    for (int kb = 0; kb < 8; kb++) {
        if (kb < 7) load_regs(kb + 1);

        const uint32_t abase = sb + (kb & 1 ? SM_A1 : SM_A0);
#pragma unroll
        for (int ks2 = 0; ks2 < 2; ks2++) {
            const int ks = kb * 2 + ks2;
            // A fragments via ldmatrix.x4 (2 m-tiles)
            uint32_t af[2][4];
#pragma unroll
            for (int mt = 0; mt < 2; mt++) {
                uint32_t aptr = abase +
                    (warpM * 32 + mt * 16 + (lane & 15)) * APITCH +
                    (lane >> 4) * 16 + ks2 * 32;
                asm volatile(
                    "ldmatrix.sync.aligned.m8n8.x4.shared.b16 {%0,%1,%2,%3}, [%4];"
                    : "=r"(af[mt][0]), "=r"(af[mt][1]),
                      "=r"(af[mt][2]), "=r"(af[mt][3]) : "r"(aptr));
            }
            // B fragments (4 n-tiles), scalar 32-bit LDS, conflict-free
            uint32_t bf[4][2];
#pragma unroll
            for (int t = 0; t < 4; t++) {
                uint32_t bptr = sb + SM_B +
                    (warpN * 32 + t * 8 + g) * BPITCH + ks * 32 + tig * 4;
                asm volatile("ld.shared.b32 %0, [%1];" : "=r"(bf[t][0]) : "r"(bptr));
                asm volatile("ld.shared.b32 %0, [%1];" : "=r"(bf[t][1]) : "r"(bptr + 16));
            }
#pragma unroll
            for (int mt = 0; mt < 2; mt++)
#pragma unroll
                for (int t = 0; t < 4; t++) {
                    asm volatile(
                        "mma.sync.aligned.m16n8k16.row.col.f32.f16.f16.f32 "
                        "{%0,%1,%2,%3}, {%4,%5,%6,%7}, {%8,%9}, {%0,%1,%2,%3};"
                        : "+f"(acc[mt][t][0]), "+f"(acc[mt][t][1]),
                          "+f"(acc[mt][t][2]), "+f"(acc[mt][t][3])
                        : "r"(af[mt][0]), "r"(af[mt][1]),
                          "r"(af[mt][2]), "r"(af[mt][3]),
                          "r"(bf[t][0]), "r"(bf[t][1]));
                }
        }
        if (kb < 7) {
            store_smem((kb + 1) & 1);
            __syncthreads();
        }
    }

    // Epilogue: cols 0-63 -> yl, 64-127 -> yr
    float* outb = (warpN < 2) ? g_yl : g_yr;
    const int colb = (warpN & 1) * 32 + tig * 2;
#pragma unroll
    for (int mt = 0; mt < 2; mt++) {
        int r0 = m0 + warpM * 32 + mt * 16 + g;
        int r1 = r0 + 8;
#pragma unroll
        for (int t = 0; t < 4; t++) {
            int col = colb + t * 8;
            if (r0 < n_nodes)
                *reinterpret_cast<float2*>(&outb[(size_t)r0 * DH + col]) =
                    make_float2(acc[mt][t][0], acc[mt][t][1]);
            if (r1 < n_nodes)
                *reinterpret_cast<float2*>(&outb[(size_t)r1 * DH + col]) =
                    make_float2(acc[mt][t][2], acc[mt][t][3]);
        }
    }
}

// ---------------------------------------------------------------------------
// Scatter1: acc1[dst] += yl[src] (16 threads/edge, red.v4) + degree
// ---------------------------------------------------------------------------
__global__ void scatter1_kernel(const int* __restrict__ src,
                                const int* __restrict__ dst, int E) {
    int t = blockIdx.x * blockDim.x + threadIdx.x;
    int e = t >> 4;
    if (e >= E) return;
    int q = t & 15;
    int s = __ldg(&src[e]);
    int d = __ldg(&dst[e]);
    float4 v = *reinterpret_cast<const float4*>(&g_yl[(size_t)s * DH + q * 4]);
    asm volatile("red.global.add.v4.f32 [%0], {%1,%2,%3,%4};"
                 :: "l"(&g_acc1[(size_t)d * DH + q * 4]),
                    "f"(v.x), "f"(v.y), "f"(v.z), "f"(v.w) : "memory");
    if (q == 0) atomicAdd(&g_deg[d], 1.0f);
}

// ---------------------------------------------------------------------------
// Combine1 + layer-2, warp-per-4-nodes. ReLU commuted past the norm scale:
//   relu(v/max(|v|,eps)) = relu(v)/max(|v|,eps)
// so z = (relu(v) @ W2) * innorm -- the sq-reduction (5 shfl) and the
// p-reduction (9 shfl) are INDEPENDENT chains that interleave.
// ---------------------------------------------------------------------------
#define C1_BLOCKS 1184
__global__ __launch_bounds__(256) void combine1_gemm2_kernel(
    const float* __restrict__ b1,
    const float* __restrict__ W2l,
    const float* __restrict__ W2r,
    int n_nodes)
{
    const int tid  = threadIdx.x;
    const int lane = tid & 31;
    const int w    = tid >> 5;
    const int k0   = lane * 2;          // this thread's two feature rows

    // preload W2 rows k0, k0+1 (8 outputs each) into registers
    float wreg[2][8];
#pragma unroll
    for (int r = 0; r < 2; r++) {
        int k = k0 + r;
#pragma unroll
        for (int j = 0; j < 8; j++)
            wreg[r][j] = (j < 4) ? __ldg(&W2l[k * DOUT + j])
                                 : __ldg(&W2r[k * DOUT + (j - 4)]);
    }
    const float bb0 = __ldg(&b1[k0]);
    const float bb1 = __ldg(&b1[k0 + 1]);

    const bool hi16 = (lane & 16) != 0;
    const bool hi8  = (lane & 8)  != 0;
    const bool hi4  = (lane & 4)  != 0;

    const int warp_g = blockIdx.x * 8 + w;
    const int stride = C1_BLOCKS * 8 * 4;

    for (int nb = warp_g * 4; nb < n_nodes; nb += stride) {
        // ---- batched loads: 4 nodes, all issued before any compute ----
        float  dg[4];
        float2 a[4], r[4];
#pragma unroll
        for (int u = 0; u < 4; u++) {
            int n = nb + u;
            int nc = (n < n_nodes) ? n : nb;   // clamp (nb always valid)
            dg[u] = g_deg[nc];
            a[u] = *reinterpret_cast<const float2*>(&g_acc1[(size_t)nc * DH + k0]);
            r[u] = *reinterpret_cast<const float2*>(&g_yr[(size_t)nc * DH + k0]);
        }

#pragma unroll
        for (int u = 0; u < 4; u++) {
            int n = nb + u;
            if (n >= n_nodes) break;
            float invd = 1.0f / fmaxf(dg[u], 1.0f);
            float v0 = fmaf(a[u].x, invd, bb0 + r[u].x);
            float v1 = fmaf(a[u].y, invd, bb1 + r[u].y);

            // independent chain 1: squared norm
            float sq = v0 * v0 + v1 * v1;
            // independent chain 2: p-partials from relu'd values
            float h0 = fmaxf(v0, 0.0f);
            float h1 = fmaxf(v1, 0.0f);
            float p[8];
#pragma unroll
            for (int j = 0; j < 8; j++)
                p[j] = fmaf(h0, wreg[0][j], h1 * wreg[1][j]);

            // interleaved butterflies (compiler schedules both chains)
#pragma unroll
            for (int o = 16; o > 0; o >>= 1)
                sq += __shfl_xor_sync(0xffffffffu, sq, o);

            float q4[4];
#pragma unroll
            for (int i = 0; i < 4; i++) {
                float send = hi16 ? p[i] : p[i + 4];
                float rcv  = __shfl_xor_sync(0xffffffffu, send, 16);
                q4[i] = (hi16 ? p[i + 4] : p[i]) + rcv;
            }
            float q2[2];
#pragma unroll
            for (int i = 0; i < 2; i++) {
                float send = hi8 ? q4[i] : q4[i + 2];
                float rcv  = __shfl_xor_sync(0xffffffffu, send, 8);
                q2[i] = (hi8 ? q4[i + 2] : q4[i]) + rcv;
            }
            float s;
            {
                float send = hi4 ? q2[0] : q2[1];
                float rcv  = __shfl_xor_sync(0xffffffffu, send, 4);
                s = (hi4 ? q2[1] : q2[0]) + rcv;
            }
            s += __shfl_xor_sync(0xffffffffu, s, 2);
            s += __shfl_xor_sync(0xffffffffu, s, 1);

            // lane 4j holds output j; scale by innorm at the end
            if ((lane & 3) == 0) {
                float innorm = 1.0f / fmaxf(sqrtf(sq), 1e-12f);
                float z = s * innorm;
                int j = lane >> 2;
                if (j < 4) g_zl[(size_t)n * DOUT + j]       = z;
                else       g_zr[(size_t)n * DOUT + (j - 4)] = z;
            }
        }
    }
}

// ---------------------------------------------------------------------------
// Scatter2: acc2[dst] += zl[src]
// ---------------------------------------------------------------------------
__global__ void scatter2_kernel(const int* __restrict__ src,
                                const int* __restrict__ dst, int E) {
    int e = blockIdx.x * blockDim.x + threadIdx.x;
    if (e >= E) return;
    int s = __ldg(&src[e]);
    int d = __ldg(&dst[e]);
    float4 v = *reinterpret_cast<const float4*>(&g_zl[(size_t)s * DOUT]);
    asm volatile("red.global.add.v4.f32 [%0], {%1,%2,%3,%4};"
                 :: "l"(&g_acc2[(size_t)d * DOUT]),
                    "f"(v.x), "f"(v.y), "f"(v.z), "f"(v.w) : "memory");
}

// ---------------------------------------------------------------------------
// Combine2: out = normalize(acc2/max(deg,1) + b2 + zr)
// ---------------------------------------------------------------------------
__global__ void combine2_kernel(const float* __restrict__ b2,
                                float* __restrict__ out, int n_nodes) {
    int n = blockIdx.x * blockDim.x + threadIdx.x;
    if (n >= n_nodes) return;
    float d = fmaxf(g_deg[n], 1.0f);
    float4 a = *reinterpret_cast<const float4*>(&g_acc2[n * DOUT]);
    float4 r = *reinterpret_cast<const float4*>(&g_zr[n * DOUT]);
    float v0 = a.x / d + b2[0] + r.x;
    float v1 = a.y / d + b2[1] + r.y;
    float v2 = a.z / d + b2[2] + r.z;
    float v3 = a.w / d + b2[3] + r.w;
    float norm = fmaxf(sqrtf(v0 * v0 + v1 * v1 + v2 * v2 + v3 * v3), 1e-12f);
    *reinterpret_cast<float4*>(&out[n * DOUT]) =
        make_float4(v0 / norm, v1 / norm, v2 / norm, v3 / norm);
}

// ---------------------------------------------------------------------------
// Launch
// ---------------------------------------------------------------------------
extern "C" void kernel_launch(void* const* d_in, const int* in_sizes, int n_in,
                              void* d_out, int out_size) {
    const float* x   = (const float*)d_in[0];
    const int*   ei  = (const int*)  d_in[1];
    const float* W1l = (const float*)d_in[2];
    const float* b1  = (const float*)d_in[3];
    const float* W1r = (const float*)d_in[4];
    const float* W2l = (const float*)d_in[5];
    const float* b2  = (const float*)d_in[6];
    const float* W2r = (const float*)d_in[7];
    float* out = (float*)d_out;

    const int N = in_sizes[0] / DIN;     // 100000
    const int E = in_sizes[1] / 2;       // 320000
    const int* src = ei;
    const int* dst = ei + E;

    cudaFuncSetAttribute(gemm1_f16_kernel,
                         cudaFuncAttributeMaxDynamicSharedMemorySize, SM_TOT);

    prep_kernel<<<(N * (DH / 4) + 255) / 256, 256>>>(W1l, W1r, N);
    gemm1_f16_kernel<<<(N + 127) / 128, 512, SM_TOT>>>(x, N);
    scatter1_kernel<<<((size_t)E * 16 + 255) / 256, 256>>>(src, dst, E);
    combine1_gemm2_kernel<<<C1_BLOCKS, 256>>>(b1, W2l, W2r, N);
    scatter2_kernel<<<(E + 255) / 256, 256>>>(src, dst, E);
    combine2_kernel<<<(N + 255) / 256, 256>>>(b2, out, N);
}